// round 16
// baseline (speedup 1.0000x reference)
#include <cuda_runtime.h>
#include <cuda_fp16.h>
#include <math.h>
#include <stdint.h>

// Problem constants
#define BN_   2
#define SQ    2048
#define DM    1024
#define NHEAD 16
#define HD    64
#define NS    (BN_*SQ)        // 4096
#define QKVD  (3*DM)          // 3072

// fp16 device-global scratch
__device__ __half g_xh[(size_t)NS * DM];
__device__ __half g_wqkv[(size_t)QKVD * DM];
__device__ __half g_wo[(size_t)DM * DM];
__device__ __half g_qkvh[(size_t)NS * QKVD];
__device__ __half g_valsh[(size_t)NS * DM];

// ---------------------------------------------------------------------------
// helpers
// ---------------------------------------------------------------------------
__device__ __forceinline__ uint32_t smem_u32(const void* p) {
    uint32_t a;
    asm("{ .reg .u64 t; cvta.to.shared.u64 t, %1; cvt.u32.u64 %0, t; }" : "=r"(a) : "l"(p));
    return a;
}
__device__ __forceinline__ uint32_t pack2(float lo, float hi) {
    __half2 h = __floats2half2_rn(lo, hi);
    return *(uint32_t*)&h;
}
__device__ __forceinline__ uint2 pack4(float4 v) {
    return make_uint2(pack2(v.x, v.y), pack2(v.z, v.w));
}
__device__ __forceinline__ void cp16(uint32_t dst, const void* src) {
    asm volatile("cp.async.cg.shared.global [%0], [%1], 16;" :: "r"(dst), "l"(src));
}
#define CP_COMMIT() asm volatile("cp.async.commit_group;" ::: "memory")
#define CP_WAIT(n)  asm volatile("cp.async.wait_group %0;" :: "n"(n) : "memory")

__device__ __forceinline__ void ldsm4(uint32_t addr, uint32_t& r0, uint32_t& r1,
                                      uint32_t& r2, uint32_t& r3) {
    asm volatile("ldmatrix.sync.aligned.m8n8.x4.shared.b16 {%0,%1,%2,%3}, [%4];"
                 : "=r"(r0), "=r"(r1), "=r"(r2), "=r"(r3) : "r"(addr));
}
__device__ __forceinline__ void ldsm4t(uint32_t addr, uint32_t& r0, uint32_t& r1,
                                       uint32_t& r2, uint32_t& r3) {
    asm volatile("ldmatrix.sync.aligned.m8n8.x4.trans.shared.b16 {%0,%1,%2,%3}, [%4];"
                 : "=r"(r0), "=r"(r1), "=r"(r2), "=r"(r3) : "r"(addr));
}
__device__ __forceinline__ void mma16(float4& d, uint32_t a0, uint32_t a1, uint32_t a2,
                                      uint32_t a3, uint32_t b0, uint32_t b1) {
    asm("mma.sync.aligned.m16n8k16.row.col.f32.f16.f16.f32 "
        "{%0,%1,%2,%3},{%4,%5,%6,%7},{%8,%9},{%0,%1,%2,%3};"
        : "+f"(d.x), "+f"(d.y), "+f"(d.z), "+f"(d.w)
        : "r"(a0), "r"(a1), "r"(a2), "r"(a3), "r"(b0), "r"(b1));
}

// ---------------------------------------------------------------------------
// merged fp32 -> fp16 conversion
// ---------------------------------------------------------------------------
#define N4_X   (NS * DM / 4)
#define N4_WQ  (QKVD * DM / 4)
#define N4_WO  (DM * DM / 4)
__global__ void f2h_all(const float* __restrict__ x, __half* __restrict__ xh,
                        const float* __restrict__ wq, __half* __restrict__ wqh,
                        const float* __restrict__ wo, __half* __restrict__ woh) {
    int i = blockIdx.x * blockDim.x + threadIdx.x;
    if (i < N4_X) {
        ((uint2*)xh)[i] = pack4(((const float4*)x)[i]);
    } else if (i < N4_X + N4_WQ) {
        int j = i - N4_X;
        ((uint2*)wqh)[j] = pack4(((const float4*)wq)[j]);
    } else if (i < N4_X + N4_WQ + N4_WO) {
        int j = i - N4_X - N4_WQ;
        ((uint2*)woh)[j] = pack4(((const float4*)wo)[j]);
    }
}
#define F2H_TOTAL (N4_X + N4_WQ + N4_WO)

#define ARS 40

// ---------------------------------------------------------------------------
// GEMM A (QKV): CTA 64x128, BK=32, 8 warps (2m x 4n, warp 32x32),
// 4-stage cp.async, 3 CTAs/SM. 1536 tiles -> 6% quantization.
// ---------------------------------------------------------------------------
#define A64_HALFS (64 * ARS)                 // 2560
#define B64_HALFS (128 * ARS)                // 5120
#define STG64_HALFS (A64_HALFS + B64_HALFS)  // 7680
#define STG64_BYTES (STG64_HALFS * 2)        // 15360
#define GEMM_SMEM (4 * STG64_BYTES)          // 61440

__global__ void __launch_bounds__(256, 3) gemm_h(const __half* __restrict__ A,
                                                 const __half* __restrict__ B,
                                                 __half* __restrict__ C,
                                                 int M, int N, int K) {
    extern __shared__ __half gsm[];

    const int tid  = threadIdx.x;
    const int lane = tid & 31;
    const int warp = tid >> 5;
    const int g    = lane >> 2;
    const int q    = lane & 3;
    const int wm   = warp & 1;
    const int wn   = warp >> 1;
    const int m0   = blockIdx.y * 64;
    const int n0   = blockIdx.x * 128;

    const int l7  = lane & 7;
    const int lb3 = (lane >> 3) & 1;
    const int lb4 = (lane >> 4) & 1;

    const uint32_t sb   = smem_u32(gsm);
    const uint32_t aoff = ((wm * 32 + l7 + 8 * lb3) * ARS + 8 * lb4) * 2;
    const uint32_t boff = ((wn * 32 + l7 + 8 * lb3) * ARS + 8 * lb4) * 2 + A64_HALFS * 2;

    float4 acc[2][4];
#pragma unroll
    for (int i = 0; i < 2; i++)
#pragma unroll
        for (int j = 0; j < 4; j++) acc[i][j] = make_float4(0.f, 0.f, 0.f, 0.f);

    const int T = K >> 5;

    auto issue = [&](int t, int buf) {
        const uint32_t db = sb + buf * STG64_BYTES;
        const int k0 = t << 5;
        {
            int r = tid >> 2, ch = tid & 3;
            cp16(db + (r * ARS + 8 * ch) * 2, A + (size_t)(m0 + r) * K + k0 + 8 * ch);
        }
#pragma unroll
        for (int p = 0; p < 2; p++) {
            int idx = tid + 256 * p;
            int r = idx >> 2, ch = idx & 3;
            cp16(db + A64_HALFS * 2 + (r * ARS + 8 * ch) * 2,
                 B + (size_t)(n0 + r) * K + k0 + 8 * ch);
        }
        CP_COMMIT();
    };

    issue(0, 0);
    issue(1, 1);
    issue(2, 2);

    for (int t = 0; t < T; t++) {
        CP_WAIT(2);
        __syncthreads();
        if (t + 3 < T) issue(t + 3, (t + 3) & 3); else CP_COMMIT();

        const uint32_t cbase = sb + (t & 3) * STG64_BYTES;
#pragma unroll
        for (int c = 0; c < 2; c++) {
            uint32_t aq[2][4], bq[2][4];
#pragma unroll
            for (int i = 0; i < 2; i++)
                ldsm4(cbase + aoff + i * (16 * ARS * 2) + c * 32,
                      aq[i][0], aq[i][1], aq[i][2], aq[i][3]);
#pragma unroll
            for (int tt = 0; tt < 2; tt++)
                ldsm4(cbase + boff + tt * (16 * ARS * 2) + c * 32,
                      bq[tt][0], bq[tt][1], bq[tt][2], bq[tt][3]);
#pragma unroll
            for (int tt = 0; tt < 2; tt++)
#pragma unroll
                for (int i = 0; i < 2; i++) {
                    mma16(acc[i][2 * tt],     aq[i][0], aq[i][1], aq[i][2], aq[i][3],
                          bq[tt][0], bq[tt][2]);
                    mma16(acc[i][2 * tt + 1], aq[i][0], aq[i][1], aq[i][2], aq[i][3],
                          bq[tt][1], bq[tt][3]);
                }
        }
    }

#pragma unroll
    for (int i = 0; i < 2; i++) {
#pragma unroll
        for (int j = 0; j < 4; j++) {
            int row = m0 + wm * 32 + 16 * i + g;
            int col = n0 + wn * 32 + 8 * j + 2 * q;
            *(uint32_t*)&C[(size_t)row * N + col]       = pack2(acc[i][j].x, acc[i][j].y);
            *(uint32_t*)&C[(size_t)(row + 8) * N + col] = pack2(acc[i][j].z, acc[i][j].w);
        }
    }
}

// ---------------------------------------------------------------------------
// GEMM B (O-proj): CTA 128x256, BK=32, 8 warps (warp 64x64), 4-stage
// cp.async, 1 CTA/SM, fp32 out. Grid = (1024/256)*(4096/128) = 128 CTAs
// = ONE wave on 148 SMs (zero tile quantization).
// ---------------------------------------------------------------------------
#define AW_HALFS (128 * ARS)                  // 5120
#define BW_HALFS (256 * ARS)                  // 10240
#define STGW_HALFS (AW_HALFS + BW_HALFS)      // 15360
#define STGW_BYTES (STGW_HALFS * 2)           // 30720
#define GEMMW_SMEM (4 * STGW_BYTES)           // 122880

__global__ void __launch_bounds__(256, 1) gemm_w(const __half* __restrict__ A,
                                                 const __half* __restrict__ B,
                                                 float* __restrict__ C,
                                                 int M, int N, int K) {
    extern __shared__ __half gsm[];

    const int tid  = threadIdx.x;
    const int lane = tid & 31;
    const int warp = tid >> 5;
    const int g    = lane >> 2;
    const int q    = lane & 3;
    const int wm   = warp >> 2;       // 0..1
    const int wn   = warp & 3;        // 0..3
    const int m0   = blockIdx.y * 128;
    const int n0   = blockIdx.x * 256;

    const int l7  = lane & 7;
    const int lb3 = (lane >> 3) & 1;
    const int lb4 = (lane >> 4) & 1;

    const uint32_t sb   = smem_u32(gsm);
    const uint32_t aoff = ((wm * 64 + l7 + 8 * lb3) * ARS + 8 * lb4) * 2;
    const uint32_t boff = ((wn * 64 + l7 + 8 * lb3) * ARS + 8 * lb4) * 2 + AW_HALFS * 2;

    float4 acc[4][8];
#pragma unroll
    for (int i = 0; i < 4; i++)
#pragma unroll
        for (int j = 0; j < 8; j++) acc[i][j] = make_float4(0.f, 0.f, 0.f, 0.f);

    const int T = K >> 5;

    auto issue = [&](int t, int buf) {
        const uint32_t db = sb + buf * STGW_BYTES;
        const int k0 = t << 5;
#pragma unroll
        for (int p = 0; p < 2; p++) {      // A: 128 rows = 512 chunks
            int idx = tid + 256 * p;
            int r = idx >> 2, ch = idx & 3;
            cp16(db + (r * ARS + 8 * ch) * 2, A + (size_t)(m0 + r) * K + k0 + 8 * ch);
        }
#pragma unroll
        for (int p = 0; p < 4; p++) {      // B: 256 rows = 1024 chunks
            int idx = tid + 256 * p;
            int r = idx >> 2, ch = idx & 3;
            cp16(db + AW_HALFS * 2 + (r * ARS + 8 * ch) * 2,
                 B + (size_t)(n0 + r) * K + k0 + 8 * ch);
        }
        CP_COMMIT();
    };

    issue(0, 0);
    issue(1, 1);
    issue(2, 2);

    for (int t = 0; t < T; t++) {
        CP_WAIT(2);
        __syncthreads();
        if (t + 3 < T) issue(t + 3, (t + 3) & 3); else CP_COMMIT();

        const uint32_t cbase = sb + (t & 3) * STGW_BYTES;
#pragma unroll
        for (int c = 0; c < 2; c++) {
            uint32_t aq[4][4], bq[4][4];
#pragma unroll
            for (int i = 0; i < 4; i++)
                ldsm4(cbase + aoff + i * (16 * ARS * 2) + c * 32,
                      aq[i][0], aq[i][1], aq[i][2], aq[i][3]);
#pragma unroll
            for (int tt = 0; tt < 4; tt++)
                ldsm4(cbase + boff + tt * (16 * ARS * 2) + c * 32,
                      bq[tt][0], bq[tt][1], bq[tt][2], bq[tt][3]);
#pragma unroll
            for (int tt = 0; tt < 4; tt++)
#pragma unroll
                for (int i = 0; i < 4; i++) {
                    mma16(acc[i][2 * tt],     aq[i][0], aq[i][1], aq[i][2], aq[i][3],
                          bq[tt][0], bq[tt][2]);
                    mma16(acc[i][2 * tt + 1], aq[i][0], aq[i][1], aq[i][2], aq[i][3],
                          bq[tt][1], bq[tt][3]);
                }
        }
    }

#pragma unroll
    for (int i = 0; i < 4; i++) {
#pragma unroll
        for (int j = 0; j < 8; j++) {
            int row = m0 + wm * 64 + 16 * i + g;
            int col = n0 + wn * 64 + 8 * j + 2 * q;
            *(float2*)&C[(size_t)row * N + col]       = make_float2(acc[i][j].x, acc[i][j].y);
            *(float2*)&C[(size_t)(row + 8) * N + col] = make_float2(acc[i][j].z, acc[i][j].w);
        }
    }
}

// ---------------------------------------------------------------------------
// Flash attention, fp16, exp2-domain. 8 warps (256 thr), q-tile 128
// (16 q-rows/warp), k-tile 64, K/V double-buffered cp.async, P in regs.
// (measured ~92% of HMMA pipe ceiling — unchanged)
// ---------------------------------------------------------------------------
#define KRS 72
#define AT_STG_HALFS (2 * 64 * KRS)         // 9216
#define AT_STG_BYTES (AT_STG_HALFS * 2)     // 18432
#define ATTN_SMEM (2 * AT_STG_BYTES)        // 36864

__global__ void __launch_bounds__(256) attn_h(const __half* __restrict__ qkv,
                                              __half* __restrict__ vals) {
    extern __shared__ __half sm[];

    const int tid  = threadIdx.x;
    const int lane = tid & 31;
    const int warp = tid >> 5;
    const int g    = lane >> 2;
    const int q    = lane & 3;
    const int l7   = lane & 7;
    const int lb3  = (lane >> 3) & 1;
    const int lb4  = (lane >> 4) & 1;

    const int nh = blockIdx.y;
    const int n  = nh >> 4;
    const int h  = nh & 15;
    const int q0 = blockIdx.x * 128;

    const __half* base = qkv + (size_t)n * SQ * QKVD + h * (3 * HD);
    const uint32_t sb = smem_u32(sm);

    // ---- stage Q
    {
        const __half* qb = base + (size_t)q0 * QKVD;
#pragma unroll
        for (int p = 0; p < 4; p++) {
            int idx = tid + 256 * p;
            int r = idx >> 3, ch = idx & 7;
            cp16(sb + (r * KRS + 8 * ch) * 2, qb + (size_t)r * QKVD + 8 * ch);
        }
        CP_COMMIT();
        CP_WAIT(0);
        __syncthreads();
    }

    uint32_t qf[4][4];
    {
        const uint32_t qbase = sb + ((warp * 16 + l7 + 8 * lb3) * KRS + 8 * lb4) * 2;
        const __half2 s2 = __float2half2_rn(0.125f * 1.44269504089f);
#pragma unroll
        for (int c = 0; c < 4; c++) {
            ldsm4(qbase + c * 32, qf[c][0], qf[c][1], qf[c][2], qf[c][3]);
#pragma unroll
            for (int k = 0; k < 4; k++) {
                __half2 v = __hmul2(*(__half2*)&qf[c][k], s2);
                qf[c][k] = *(uint32_t*)&v;
            }
        }
    }
    __syncthreads();

    const uint32_t koff = ((l7 + 8 * lb3) * KRS + 8 * lb4) * 2;
    const uint32_t voff = 64 * KRS * 2 + ((l7 + 8 * lb4) * KRS + 8 * lb3) * 2;

    auto issue_kv = [&](int kb, int buf) {
        const uint32_t db = sb + buf * AT_STG_BYTES;
        const __half* kvb = base + (size_t)(kb * 64) * QKVD;
#pragma unroll
        for (int p = 0; p < 2; p++) {
            int idx = tid + 256 * p;
            int r = idx >> 3, ch = idx & 7;
            const __half* rp = kvb + (size_t)r * QKVD;
            cp16(db + (r * KRS + 8 * ch) * 2,            rp + HD + 8 * ch);
            cp16(db + (64 * KRS + r * KRS + 8 * ch) * 2, rp + 2 * HD + 8 * ch);
        }
        CP_COMMIT();
    };

    float m0r = -INFINITY, m1r = -INFINITY, l0s = 0.f, l1s = 0.f;
    float4 oacc[8];
#pragma unroll
    for (int j = 0; j < 8; j++) oacc[j] = make_float4(0.f, 0.f, 0.f, 0.f);

    issue_kv(0, 0);

    for (int kb = 0; kb < SQ / 64; kb++) {
        CP_WAIT(0);
        __syncthreads();
        if (kb + 1 < SQ / 64) issue_kv(kb + 1, (kb + 1) & 1);

        const uint32_t cbase = sb + (kb & 1) * AT_STG_BYTES;

        // ---- S = Q K^T
        float4 sc[8];
#pragma unroll
        for (int j = 0; j < 8; j++) sc[j] = make_float4(0.f, 0.f, 0.f, 0.f);
#pragma unroll
        for (int c = 0; c < 4; c++)
#pragma unroll
            for (int tt = 0; tt < 4; tt++) {
                uint32_t b0, b1, b2, b3;
                ldsm4(cbase + koff + tt * (16 * KRS * 2) + c * 32, b0, b1, b2, b3);
                mma16(sc[2 * tt],     qf[c][0], qf[c][1], qf[c][2], qf[c][3], b0, b2);
                mma16(sc[2 * tt + 1], qf[c][0], qf[c][1], qf[c][2], qf[c][3], b1, b3);
            }

        // ---- online softmax (exp2); P packed into A-fragments
        uint32_t pf[4][4];
        {
            float mx0 = -INFINITY, mx1 = -INFINITY;
#pragma unroll
            for (int j = 0; j < 8; j++) {
                mx0 = fmaxf(mx0, fmaxf(sc[j].x, sc[j].y));
                mx1 = fmaxf(mx1, fmaxf(sc[j].z, sc[j].w));
            }
#pragma unroll
            for (int off = 1; off <= 2; off <<= 1) {
                mx0 = fmaxf(mx0, __shfl_xor_sync(0xffffffffu, mx0, off));
                mx1 = fmaxf(mx1, __shfl_xor_sync(0xffffffffu, mx1, off));
            }
            float mn0 = fmaxf(m0r, mx0), mn1 = fmaxf(m1r, mx1);
            float corr0 = exp2f(m0r - mn0), corr1 = exp2f(m1r - mn1);

            float rs0 = 0.f, rs1 = 0.f;
#pragma unroll
            for (int j = 0; j < 8; j++) {
                float p0 = exp2f(sc[j].x - mn0);
                float p1 = exp2f(sc[j].y - mn0);
                float p2 = exp2f(sc[j].z - mn1);
                float p3 = exp2f(sc[j].w - mn1);
                rs0 += p0 + p1; rs1 += p2 + p3;
                int c = j >> 1;
                if ((j & 1) == 0) { pf[c][0] = pack2(p0, p1); pf[c][1] = pack2(p2, p3); }
                else              { pf[c][2] = pack2(p0, p1); pf[c][3] = pack2(p2, p3); }
            }
#pragma unroll
            for (int off = 1; off <= 2; off <<= 1) {
                rs0 += __shfl_xor_sync(0xffffffffu, rs0, off);
                rs1 += __shfl_xor_sync(0xffffffffu, rs1, off);
            }
            l0s = l0s * corr0 + rs0;  m0r = mn0;
            l1s = l1s * corr1 + rs1;  m1r = mn1;
#pragma unroll
            for (int j = 0; j < 8; j++) {
                oacc[j].x *= corr0; oacc[j].y *= corr0;
                oacc[j].z *= corr1; oacc[j].w *= corr1;
            }
        }

        // ---- O += P V
#pragma unroll
        for (int c = 0; c < 4; c++)
#pragma unroll
            for (int td = 0; td < 4; td++) {
                uint32_t v0, v1, v2, v3;
                ldsm4t(cbase + voff + c * (16 * KRS * 2) + td * 32, v0, v1, v2, v3);
                mma16(oacc[2 * td],     pf[c][0], pf[c][1], pf[c][2], pf[c][3], v0, v2);
                mma16(oacc[2 * td + 1], pf[c][0], pf[c][1], pf[c][2], pf[c][3], v1, v3);
            }
    }

    // ---- normalize + write fp16
    __half* obase = vals + (size_t)(n * SQ + q0) * DM + h * HD;
    {
        int r = warp * 16 + g;
        float inv0 = 1.0f / l0s, inv1 = 1.0f / l1s;
#pragma unroll
        for (int j = 0; j < 8; j++) {
            int col = 8 * j + 2 * q;
            *(uint32_t*)&obase[(size_t)r * DM + col] =
                pack2(oacc[j].x * inv0, oacc[j].y * inv0);
            *(uint32_t*)&obase[(size_t)(r + 8) * DM + col] =
                pack2(oacc[j].z * inv1, oacc[j].w * inv1);
        }
    }
}

// ---------------------------------------------------------------------------
extern "C" void kernel_launch(void* const* d_in, const int* in_sizes, int n_in,
                              void* d_out, int out_size) {
    const float* x     = (const float*)d_in[0];
    const float* qkv_w = (const float*)d_in[1];
    const float* o_w   = (const float*)d_in[2];
    float* out = (float*)d_out;

    __half *xh, *wqkv, *wo, *qkvh, *valsh;
    cudaGetSymbolAddress((void**)&xh,    g_xh);
    cudaGetSymbolAddress((void**)&wqkv,  g_wqkv);
    cudaGetSymbolAddress((void**)&wo,    g_wo);
    cudaGetSymbolAddress((void**)&qkvh,  g_qkvh);
    cudaGetSymbolAddress((void**)&valsh, g_valsh);

    cudaFuncSetAttribute(gemm_h, cudaFuncAttributeMaxDynamicSharedMemorySize, GEMM_SMEM);
    cudaFuncSetAttribute(gemm_w, cudaFuncAttributeMaxDynamicSharedMemorySize, GEMMW_SMEM);
    cudaFuncSetAttribute(attn_h, cudaFuncAttributeMaxDynamicSharedMemorySize, ATTN_SMEM);

    // 0) fp32 -> fp16 conversions (single launch)
    f2h_all<<<(F2H_TOTAL + 255) / 256, 256>>>(x, xh, qkv_w, wqkv, o_w, wo);

    // 1) QKV projection (fp16 out): 24 x 64 = 1536 tiles of 64x128
    gemm_h<<<dim3(QKVD / 128, NS / 64), 256, GEMM_SMEM>>>(xh, wqkv, qkvh, NS, QKVD, DM);
    // 2) Attention (fp16 in/out)
    attn_h<<<dim3(SQ / 128, BN_ * NHEAD), 256, ATTN_SMEM>>>(qkvh, valsh);
    // 3) Output projection (fp32 out): 4 x 32 = 128 tiles of 128x256 = 1 wave
    gemm_w<<<dim3(DM / 256, NS / 128), 256, GEMMW_SMEM>>>(valsh, wo, out, NS, DM, DM);
}

// round 17
// speedup vs baseline: 1.5358x; 1.5358x over previous
#include <cuda_runtime.h>
#include <cuda_fp16.h>
#include <math.h>
#include <stdint.h>

// Problem constants
#define BN_   2
#define SQ    2048
#define DM    1024
#define NHEAD 16
#define HD    64
#define NS    (BN_*SQ)        // 4096
#define QKVD  (3*DM)          // 3072

// fp16 device-global scratch
__device__ __half g_xh[(size_t)NS * DM];
__device__ __half g_wqkv[(size_t)QKVD * DM];
__device__ __half g_wo[(size_t)DM * DM];
__device__ __half g_qkvh[(size_t)NS * QKVD];
__device__ __half g_valsh[(size_t)NS * DM];

// ---------------------------------------------------------------------------
// helpers
// ---------------------------------------------------------------------------
__device__ __forceinline__ uint32_t smem_u32(const void* p) {
    uint32_t a;
    asm("{ .reg .u64 t; cvta.to.shared.u64 t, %1; cvt.u32.u64 %0, t; }" : "=r"(a) : "l"(p));
    return a;
}
__device__ __forceinline__ uint32_t pack2(float lo, float hi) {
    __half2 h = __floats2half2_rn(lo, hi);
    return *(uint32_t*)&h;
}
__device__ __forceinline__ uint2 pack4(float4 v) {
    return make_uint2(pack2(v.x, v.y), pack2(v.z, v.w));
}
__device__ __forceinline__ void cp16(uint32_t dst, const void* src) {
    asm volatile("cp.async.cg.shared.global [%0], [%1], 16;" :: "r"(dst), "l"(src));
}
#define CP_COMMIT() asm volatile("cp.async.commit_group;" ::: "memory")
#define CP_WAIT(n)  asm volatile("cp.async.wait_group %0;" :: "n"(n) : "memory")

__device__ __forceinline__ void ldsm4(uint32_t addr, uint32_t& r0, uint32_t& r1,
                                      uint32_t& r2, uint32_t& r3) {
    asm volatile("ldmatrix.sync.aligned.m8n8.x4.shared.b16 {%0,%1,%2,%3}, [%4];"
                 : "=r"(r0), "=r"(r1), "=r"(r2), "=r"(r3) : "r"(addr));
}
__device__ __forceinline__ void ldsm4t(uint32_t addr, uint32_t& r0, uint32_t& r1,
                                       uint32_t& r2, uint32_t& r3) {
    asm volatile("ldmatrix.sync.aligned.m8n8.x4.trans.shared.b16 {%0,%1,%2,%3}, [%4];"
                 : "=r"(r0), "=r"(r1), "=r"(r2), "=r"(r3) : "r"(addr));
}
__device__ __forceinline__ void mma16(float4& d, uint32_t a0, uint32_t a1, uint32_t a2,
                                      uint32_t a3, uint32_t b0, uint32_t b1) {
    asm("mma.sync.aligned.m16n8k16.row.col.f32.f16.f16.f32 "
        "{%0,%1,%2,%3},{%4,%5,%6,%7},{%8,%9},{%0,%1,%2,%3};"
        : "+f"(d.x), "+f"(d.y), "+f"(d.z), "+f"(d.w)
        : "r"(a0), "r"(a1), "r"(a2), "r"(a3), "r"(b0), "r"(b1));
}

// ---------------------------------------------------------------------------
// merged fp32 -> fp16 conversion
// ---------------------------------------------------------------------------
#define N4_X   (NS * DM / 4)
#define N4_WQ  (QKVD * DM / 4)
#define N4_WO  (DM * DM / 4)
__global__ void f2h_all(const float* __restrict__ x, __half* __restrict__ xh,
                        const float* __restrict__ wq, __half* __restrict__ wqh,
                        const float* __restrict__ wo, __half* __restrict__ woh) {
    int i = blockIdx.x * blockDim.x + threadIdx.x;
    if (i < N4_X) {
        ((uint2*)xh)[i] = pack4(((const float4*)x)[i]);
    } else if (i < N4_X + N4_WQ) {
        int j = i - N4_X;
        ((uint2*)wqh)[j] = pack4(((const float4*)wq)[j]);
    } else if (i < N4_X + N4_WQ + N4_WO) {
        int j = i - N4_X - N4_WQ;
        ((uint2*)woh)[j] = pack4(((const float4*)wo)[j]);
    }
}
#define F2H_TOTAL (N4_X + N4_WQ + N4_WO)

#define ARS 40

// ---------------------------------------------------------------------------
// GEMM A (QKV): CTA 64x128, BK=32, 8 warps (2m x 4n, warp 32x32),
// 4-stage cp.async, 3 CTAs/SM, fp16 out. (R15 best for QKV: ~107us)
// ---------------------------------------------------------------------------
#define A64_HALFS (64 * ARS)                 // 2560
#define B64_HALFS (128 * ARS)                // 5120
#define STG64_HALFS (A64_HALFS + B64_HALFS)  // 7680
#define STG64_BYTES (STG64_HALFS * 2)        // 15360
#define GEMM_SMEM (4 * STG64_BYTES)          // 61440

__global__ void __launch_bounds__(256, 3) gemm_h(const __half* __restrict__ A,
                                                 const __half* __restrict__ B,
                                                 __half* __restrict__ C,
                                                 int M, int N, int K) {
    extern __shared__ __half gsm[];

    const int tid  = threadIdx.x;
    const int lane = tid & 31;
    const int warp = tid >> 5;
    const int g    = lane >> 2;
    const int q    = lane & 3;
    const int wm   = warp & 1;
    const int wn   = warp >> 1;
    const int m0   = blockIdx.y * 64;
    const int n0   = blockIdx.x * 128;

    const int l7  = lane & 7;
    const int lb3 = (lane >> 3) & 1;
    const int lb4 = (lane >> 4) & 1;

    const uint32_t sb   = smem_u32(gsm);
    const uint32_t aoff = ((wm * 32 + l7 + 8 * lb3) * ARS + 8 * lb4) * 2;
    const uint32_t boff = ((wn * 32 + l7 + 8 * lb3) * ARS + 8 * lb4) * 2 + A64_HALFS * 2;

    float4 acc[2][4];
#pragma unroll
    for (int i = 0; i < 2; i++)
#pragma unroll
        for (int j = 0; j < 4; j++) acc[i][j] = make_float4(0.f, 0.f, 0.f, 0.f);

    const int T = K >> 5;

    auto issue = [&](int t, int buf) {
        const uint32_t db = sb + buf * STG64_BYTES;
        const int k0 = t << 5;
        {
            int r = tid >> 2, ch = tid & 3;
            cp16(db + (r * ARS + 8 * ch) * 2, A + (size_t)(m0 + r) * K + k0 + 8 * ch);
        }
#pragma unroll
        for (int p = 0; p < 2; p++) {
            int idx = tid + 256 * p;
            int r = idx >> 2, ch = idx & 3;
            cp16(db + A64_HALFS * 2 + (r * ARS + 8 * ch) * 2,
                 B + (size_t)(n0 + r) * K + k0 + 8 * ch);
        }
        CP_COMMIT();
    };

    issue(0, 0);
    issue(1, 1);
    issue(2, 2);

    for (int t = 0; t < T; t++) {
        CP_WAIT(2);
        __syncthreads();
        if (t + 3 < T) issue(t + 3, (t + 3) & 3); else CP_COMMIT();

        const uint32_t cbase = sb + (t & 3) * STG64_BYTES;
#pragma unroll
        for (int c = 0; c < 2; c++) {
            uint32_t aq[2][4], bq[2][4];
#pragma unroll
            for (int i = 0; i < 2; i++)
                ldsm4(cbase + aoff + i * (16 * ARS * 2) + c * 32,
                      aq[i][0], aq[i][1], aq[i][2], aq[i][3]);
#pragma unroll
            for (int tt = 0; tt < 2; tt++)
                ldsm4(cbase + boff + tt * (16 * ARS * 2) + c * 32,
                      bq[tt][0], bq[tt][1], bq[tt][2], bq[tt][3]);
#pragma unroll
            for (int tt = 0; tt < 2; tt++)
#pragma unroll
                for (int i = 0; i < 2; i++) {
                    mma16(acc[i][2 * tt],     aq[i][0], aq[i][1], aq[i][2], aq[i][3],
                          bq[tt][0], bq[tt][2]);
                    mma16(acc[i][2 * tt + 1], aq[i][0], aq[i][1], aq[i][2], aq[i][3],
                          bq[tt][1], bq[tt][3]);
                }
        }
    }

#pragma unroll
    for (int i = 0; i < 2; i++) {
#pragma unroll
        for (int j = 0; j < 4; j++) {
            int row = m0 + wm * 32 + 16 * i + g;
            int col = n0 + wn * 32 + 8 * j + 2 * q;
            *(uint32_t*)&C[(size_t)row * N + col]       = pack2(acc[i][j].x, acc[i][j].y);
            *(uint32_t*)&C[(size_t)(row + 8) * N + col] = pack2(acc[i][j].z, acc[i][j].w);
        }
    }
}

// ---------------------------------------------------------------------------
// GEMM B (O-proj): CTA 128x128, BK=32, 8 warps (warp 64x32), 4-stage
// cp.async, 2 CTAs/SM, fp32 out. (R12 best for O-proj: 40.0us)
// ---------------------------------------------------------------------------
#define A128_HALFS (128 * ARS)                  // 5120
#define STG128_HALFS (2 * A128_HALFS)           // 10240
#define STG128_BYTES (STG128_HALFS * 2)         // 20480
#define GEMMO_SMEM (4 * STG128_BYTES)           // 81920

__global__ void __launch_bounds__(256, 2) gemm_o(const __half* __restrict__ A,
                                                 const __half* __restrict__ B,
                                                 float* __restrict__ C,
                                                 int M, int N, int K) {
    extern __shared__ __half gsm[];

    const int tid  = threadIdx.x;
    const int lane = tid & 31;
    const int warp = tid >> 5;
    const int g    = lane >> 2;
    const int q    = lane & 3;
    const int wm   = warp >> 2;
    const int wn   = warp & 3;
    const int m0   = blockIdx.y * 128;
    const int n0   = blockIdx.x * 128;

    const int l7  = lane & 7;
    const int lb3 = (lane >> 3) & 1;
    const int lb4 = (lane >> 4) & 1;

    const uint32_t sb   = smem_u32(gsm);
    const uint32_t aoff = ((wm * 64 + l7 + 8 * lb3) * ARS + 8 * lb4) * 2;
    const uint32_t boff = ((wn * 32 + l7 + 8 * lb3) * ARS + 8 * lb4) * 2 + A128_HALFS * 2;

    float4 acc[4][4];
#pragma unroll
    for (int i = 0; i < 4; i++)
#pragma unroll
        for (int j = 0; j < 4; j++) acc[i][j] = make_float4(0.f, 0.f, 0.f, 0.f);

    const int T = K >> 5;

    auto issue = [&](int t, int buf) {
        const uint32_t db = sb + buf * STG128_BYTES;
        const int k0 = t << 5;
#pragma unroll
        for (int p = 0; p < 2; p++) {
            int idx = tid + 256 * p;
            int r = idx >> 2, ch = idx & 3;
            cp16(db + (r * ARS + 8 * ch) * 2, A + (size_t)(m0 + r) * K + k0 + 8 * ch);
        }
#pragma unroll
        for (int p = 0; p < 2; p++) {
            int idx = tid + 256 * p;
            int r = idx >> 2, ch = idx & 3;
            cp16(db + A128_HALFS * 2 + (r * ARS + 8 * ch) * 2,
                 B + (size_t)(n0 + r) * K + k0 + 8 * ch);
        }
        CP_COMMIT();
    };

    issue(0, 0);
    issue(1, 1);
    issue(2, 2);

    for (int t = 0; t < T; t++) {
        CP_WAIT(2);
        __syncthreads();
        if (t + 3 < T) issue(t + 3, (t + 3) & 3); else CP_COMMIT();

        const uint32_t cbase = sb + (t & 3) * STG128_BYTES;
#pragma unroll
        for (int c = 0; c < 2; c++) {
            uint32_t aq[4][4], bq[2][4];
#pragma unroll
            for (int i = 0; i < 4; i++)
                ldsm4(cbase + aoff + i * (16 * ARS * 2) + c * 32,
                      aq[i][0], aq[i][1], aq[i][2], aq[i][3]);
#pragma unroll
            for (int tt = 0; tt < 2; tt++)
                ldsm4(cbase + boff + tt * (16 * ARS * 2) + c * 32,
                      bq[tt][0], bq[tt][1], bq[tt][2], bq[tt][3]);
#pragma unroll
            for (int tt = 0; tt < 2; tt++)
#pragma unroll
                for (int i = 0; i < 4; i++) {
                    mma16(acc[i][2 * tt],     aq[i][0], aq[i][1], aq[i][2], aq[i][3],
                          bq[tt][0], bq[tt][2]);
                    mma16(acc[i][2 * tt + 1], aq[i][0], aq[i][1], aq[i][2], aq[i][3],
                          bq[tt][1], bq[tt][3]);
                }
        }
    }

#pragma unroll
    for (int i = 0; i < 4; i++) {
#pragma unroll
        for (int j = 0; j < 4; j++) {
            int row = m0 + wm * 64 + 16 * i + g;
            int col = n0 + wn * 32 + 8 * j + 2 * q;
            *(float2*)&C[(size_t)row * N + col]       = make_float2(acc[i][j].x, acc[i][j].y);
            *(float2*)&C[(size_t)(row + 8) * N + col] = make_float2(acc[i][j].z, acc[i][j].w);
        }
    }
}

// ---------------------------------------------------------------------------
// Flash attention, fp16, exp2-domain. 8 warps (256 thr), q-tile 128
// (16 q-rows/warp), k-tile 64, K/V double-buffered cp.async, P in regs.
// ---------------------------------------------------------------------------
#define KRS 72
#define AT_STG_HALFS (2 * 64 * KRS)         // 9216
#define AT_STG_BYTES (AT_STG_HALFS * 2)     // 18432
#define ATTN_SMEM (2 * AT_STG_BYTES)        // 36864

__global__ void __launch_bounds__(256) attn_h(const __half* __restrict__ qkv,
                                              __half* __restrict__ vals) {
    extern __shared__ __half sm[];

    const int tid  = threadIdx.x;
    const int lane = tid & 31;
    const int warp = tid >> 5;
    const int g    = lane >> 2;
    const int q    = lane & 3;
    const int l7   = lane & 7;
    const int lb3  = (lane >> 3) & 1;
    const int lb4  = (lane >> 4) & 1;

    const int nh = blockIdx.y;
    const int n  = nh >> 4;
    const int h  = nh & 15;
    const int q0 = blockIdx.x * 128;

    const __half* base = qkv + (size_t)n * SQ * QKVD + h * (3 * HD);
    const uint32_t sb = smem_u32(sm);

    // ---- stage Q
    {
        const __half* qb = base + (size_t)q0 * QKVD;
#pragma unroll
        for (int p = 0; p < 4; p++) {
            int idx = tid + 256 * p;
            int r = idx >> 3, ch = idx & 7;
            cp16(sb + (r * KRS + 8 * ch) * 2, qb + (size_t)r * QKVD + 8 * ch);
        }
        CP_COMMIT();
        CP_WAIT(0);
        __syncthreads();
    }

    uint32_t qf[4][4];
    {
        const uint32_t qbase = sb + ((warp * 16 + l7 + 8 * lb3) * KRS + 8 * lb4) * 2;
        const __half2 s2 = __float2half2_rn(0.125f * 1.44269504089f);
#pragma unroll
        for (int c = 0; c < 4; c++) {
            ldsm4(qbase + c * 32, qf[c][0], qf[c][1], qf[c][2], qf[c][3]);
#pragma unroll
            for (int k = 0; k < 4; k++) {
                __half2 v = __hmul2(*(__half2*)&qf[c][k], s2);
                qf[c][k] = *(uint32_t*)&v;
            }
        }
    }
    __syncthreads();

    const uint32_t koff = ((l7 + 8 * lb3) * KRS + 8 * lb4) * 2;
    const uint32_t voff = 64 * KRS * 2 + ((l7 + 8 * lb4) * KRS + 8 * lb3) * 2;

    auto issue_kv = [&](int kb, int buf) {
        const uint32_t db = sb + buf * AT_STG_BYTES;
        const __half* kvb = base + (size_t)(kb * 64) * QKVD;
#pragma unroll
        for (int p = 0; p < 2; p++) {
            int idx = tid + 256 * p;
            int r = idx >> 3, ch = idx & 7;
            const __half* rp = kvb + (size_t)r * QKVD;
            cp16(db + (r * KRS + 8 * ch) * 2,            rp + HD + 8 * ch);
            cp16(db + (64 * KRS + r * KRS + 8 * ch) * 2, rp + 2 * HD + 8 * ch);
        }
        CP_COMMIT();
    };

    float m0r = -INFINITY, m1r = -INFINITY, l0s = 0.f, l1s = 0.f;
    float4 oacc[8];
#pragma unroll
    for (int j = 0; j < 8; j++) oacc[j] = make_float4(0.f, 0.f, 0.f, 0.f);

    issue_kv(0, 0);

    for (int kb = 0; kb < SQ / 64; kb++) {
        CP_WAIT(0);
        __syncthreads();
        if (kb + 1 < SQ / 64) issue_kv(kb + 1, (kb + 1) & 1);

        const uint32_t cbase = sb + (kb & 1) * AT_STG_BYTES;

        // ---- S = Q K^T
        float4 sc[8];
#pragma unroll
        for (int j = 0; j < 8; j++) sc[j] = make_float4(0.f, 0.f, 0.f, 0.f);
#pragma unroll
        for (int c = 0; c < 4; c++)
#pragma unroll
            for (int tt = 0; tt < 4; tt++) {
                uint32_t b0, b1, b2, b3;
                ldsm4(cbase + koff + tt * (16 * KRS * 2) + c * 32, b0, b1, b2, b3);
                mma16(sc[2 * tt],     qf[c][0], qf[c][1], qf[c][2], qf[c][3], b0, b2);
                mma16(sc[2 * tt + 1], qf[c][0], qf[c][1], qf[c][2], qf[c][3], b1, b3);
            }

        // ---- online softmax (exp2); P packed into A-fragments
        uint32_t pf[4][4];
        {
            float mx0 = -INFINITY, mx1 = -INFINITY;
#pragma unroll
            for (int j = 0; j < 8; j++) {
                mx0 = fmaxf(mx0, fmaxf(sc[j].x, sc[j].y));
                mx1 = fmaxf(mx1, fmaxf(sc[j].z, sc[j].w));
            }
#pragma unroll
            for (int off = 1; off <= 2; off <<= 1) {
                mx0 = fmaxf(mx0, __shfl_xor_sync(0xffffffffu, mx0, off));
                mx1 = fmaxf(mx1, __shfl_xor_sync(0xffffffffu, mx1, off));
            }
            float mn0 = fmaxf(m0r, mx0), mn1 = fmaxf(m1r, mx1);
            float corr0 = exp2f(m0r - mn0), corr1 = exp2f(m1r - mn1);

            float rs0 = 0.f, rs1 = 0.f;
#pragma unroll
            for (int j = 0; j < 8; j++) {
                float p0 = exp2f(sc[j].x - mn0);
                float p1 = exp2f(sc[j].y - mn0);
                float p2 = exp2f(sc[j].z - mn1);
                float p3 = exp2f(sc[j].w - mn1);
                rs0 += p0 + p1; rs1 += p2 + p3;
                int c = j >> 1;
                if ((j & 1) == 0) { pf[c][0] = pack2(p0, p1); pf[c][1] = pack2(p2, p3); }
                else              { pf[c][2] = pack2(p0, p1); pf[c][3] = pack2(p2, p3); }
            }
#pragma unroll
            for (int off = 1; off <= 2; off <<= 1) {
                rs0 += __shfl_xor_sync(0xffffffffu, rs0, off);
                rs1 += __shfl_xor_sync(0xffffffffu, rs1, off);
            }
            l0s = l0s * corr0 + rs0;  m0r = mn0;
            l1s = l1s * corr1 + rs1;  m1r = mn1;
#pragma unroll
            for (int j = 0; j < 8; j++) {
                oacc[j].x *= corr0; oacc[j].y *= corr0;
                oacc[j].z *= corr1; oacc[j].w *= corr1;
            }
        }

        // ---- O += P V
#pragma unroll
        for (int c = 0; c < 4; c++)
#pragma unroll
            for (int td = 0; td < 4; td++) {
                uint32_t v0, v1, v2, v3;
                ldsm4t(cbase + voff + c * (16 * KRS * 2) + td * 32, v0, v1, v2, v3);
                mma16(oacc[2 * td],     pf[c][0], pf[c][1], pf[c][2], pf[c][3], v0, v2);
                mma16(oacc[2 * td + 1], pf[c][0], pf[c][1], pf[c][2], pf[c][3], v1, v3);
            }
    }

    // ---- normalize + write fp16
    __half* obase = vals + (size_t)(n * SQ + q0) * DM + h * HD;
    {
        int r = warp * 16 + g;
        float inv0 = 1.0f / l0s, inv1 = 1.0f / l1s;
#pragma unroll
        for (int j = 0; j < 8; j++) {
            int col = 8 * j + 2 * q;
            *(uint32_t*)&obase[(size_t)r * DM + col] =
                pack2(oacc[j].x * inv0, oacc[j].y * inv0);
            *(uint32_t*)&obase[(size_t)(r + 8) * DM + col] =
                pack2(oacc[j].z * inv1, oacc[j].w * inv1);
        }
    }
}

// ---------------------------------------------------------------------------
extern "C" void kernel_launch(void* const* d_in, const int* in_sizes, int n_in,
                              void* d_out, int out_size) {
    const float* x     = (const float*)d_in[0];
    const float* qkv_w = (const float*)d_in[1];
    const float* o_w   = (const float*)d_in[2];
    float* out = (float*)d_out;

    __half *xh, *wqkv, *wo, *qkvh, *valsh;
    cudaGetSymbolAddress((void**)&xh,    g_xh);
    cudaGetSymbolAddress((void**)&wqkv,  g_wqkv);
    cudaGetSymbolAddress((void**)&wo,    g_wo);
    cudaGetSymbolAddress((void**)&qkvh,  g_qkvh);
    cudaGetSymbolAddress((void**)&valsh, g_valsh);

    cudaFuncSetAttribute(gemm_h, cudaFuncAttributeMaxDynamicSharedMemorySize, GEMM_SMEM);
    cudaFuncSetAttribute(gemm_o, cudaFuncAttributeMaxDynamicSharedMemorySize, GEMMO_SMEM);
    cudaFuncSetAttribute(attn_h, cudaFuncAttributeMaxDynamicSharedMemorySize, ATTN_SMEM);

    // 0) fp32 -> fp16 conversions (single launch)
    f2h_all<<<(F2H_TOTAL + 255) / 256, 256>>>(x, xh, qkv_w, wqkv, o_w, wo);

    // 1) QKV projection (fp16 out): 1536 tiles of 64x128, 3 CTAs/SM
    gemm_h<<<dim3(QKVD / 128, NS / 64), 256, GEMM_SMEM>>>(xh, wqkv, qkvh, NS, QKVD, DM);
    // 2) Attention (fp16 in/out)
    attn_h<<<dim3(SQ / 128, BN_ * NHEAD), 256, ATTN_SMEM>>>(qkvh, valsh);
    // 3) Output projection (fp32 out): 256 tiles of 128x128, 2 CTAs/SM
    gemm_o<<<dim3(DM / 128, NS / 128), 256, GEMMO_SMEM>>>(valsh, wo, out, NS, DM, DM);
}